// round 13
// baseline (speedup 1.0000x reference)
#include <cuda_runtime.h>
#include <cstdint>
#include <cfloat>

#define NS 16384
#define NQ 16384
#define DIM 64
#define NC 64
#define QT 64
#define ST 128
#define NCHUNK (NS / ST)          // 128

// ---------------- device scratch ----------------
__device__ __align__(16) float g_sq_s[NS];
__device__ int g_lab[NS];

// ---------------- helpers ----------------
__device__ __forceinline__ uint32_t smem_u32(const void* p) {
    uint32_t a;
    asm("{ .reg .u64 t; cvta.to.shared.u64 t, %1; cvt.u32.u64 %0, t; }" : "=r"(a) : "l"(p));
    return a;
}
__device__ __forceinline__ unsigned long long fma2(unsigned long long a,
                                                   unsigned long long b,
                                                   unsigned long long c) {
    unsigned long long d;
    asm("fma.rn.f32x2 %0, %1, %2, %3;" : "=l"(d) : "l"(a), "l"(b), "l"(c));
    return d;
}

// ---------------- prep: ||s||^2 + labels (4 threads per support row) ------
__global__ __launch_bounds__(256) void prep_kernel(const float* __restrict__ S,
                                                   const float* __restrict__ OH) {
    int gid = blockIdx.x * blockDim.x + threadIdx.x;   // 65536 threads
    int row = gid >> 2;
    int seg = gid & 3;
    int kb  = seg * 16;

    float ps = 0.f;
    #pragma unroll
    for (int i = 0; i < 4; i++) {
        float4 sv = *(const float4*)(S + (size_t)row * DIM + kb + i * 4);
        ps += sv.x * sv.x + sv.y * sv.y + sv.z * sv.z + sv.w * sv.w;
    }
    #pragma unroll
    for (int off = 1; off <= 2; off <<= 1)
        ps += __shfl_xor_sync(0xffffffffu, ps, off);

    float best = -1.f;
    int bi = kb;
    const float4* oh = (const float4*)(OH + (size_t)row * NC + kb);
    #pragma unroll
    for (int i = 0; i < 4; i++) {
        float4 v = oh[i];
        float vv[4] = {v.x, v.y, v.z, v.w};
        #pragma unroll
        for (int j = 0; j < 4; j++)
            if (vv[j] > best) { best = vv[j]; bi = kb + i * 4 + j; }
    }
    #pragma unroll
    for (int off = 1; off <= 2; off <<= 1) {
        float ob = __shfl_xor_sync(0xffffffffu, best, off);
        int   oi = __shfl_xor_sync(0xffffffffu, bi, off);
        if (ob > best || (ob == best && oi < bi)) { best = ob; bi = oi; }
    }
    if (seg == 0) { g_sq_s[row] = ps; g_lab[row] = bi; }
}

// ---------------- main FFMA2 kernel ----------------
// smem: Qdup 32KB | Ss 2x32KB | sqs 2x512B | pm/pi 2KB | lab 256B  -> 99.2KB
#define OFF_Q   0
#define OFF_S   32768
#define OFF_SQ  98304
#define OFF_PM  99328
#define OFF_PI  100352
#define OFF_LAB 101376
#define SMEM_SZ 101632

__global__ __launch_bounds__(256, 2) void knn_kernel(const float* __restrict__ S,
                                                     const float* __restrict__ Q,
                                                     float* __restrict__ out) {
    extern __shared__ __align__(16) char smem[];
    const uint32_t sbase = smem_u32(smem);
    const int tid  = threadIdx.x;
    const int lane = tid & 31;
    const int w    = tid >> 5;
    const int qs   = w & 1;          // query strip: [qs*32, +32)
    const int ss   = w >> 1;         // support strip: [ss*32, +32)
    const int qg   = lane & 7;       // 4 queries: qs*32 + qg*4 + i
    const int sg   = lane >> 3;      // 8 supports: ss*32 + sg*8 + j
    const int qbase = blockIdx.x * QT;

    float* Qdup   = (float*)(smem + OFF_Q);     // [64 k][128] duplicated
    float* Ssm    = (float*)(smem + OFF_S);     // [2][64 k][128] swizzled transpose
    float* sqs_sm = (float*)(smem + OFF_SQ);

    // ---- Q tile: transpose + duplicate ----
    #pragma unroll
    for (int j = 0; j < 4; j++) {
        int g = tid + j * 256;
        int q = g >> 4;
        int k4 = (g & 15) * 4;
        float4 v = *(const float4*)(Q + (size_t)(qbase + q) * DIM + k4);
        float vv[4] = {v.x, v.y, v.z, v.w};
        #pragma unroll
        for (int cc = 0; cc < 4; cc++) {
            uint32_t b = __float_as_uint(vv[cc]);
            unsigned long long d = ((unsigned long long)b << 32) | b;
            *(unsigned long long*)(Qdup + (k4 + cc) * 128 + 2 * q) = d;
        }
    }

    // ---- S staging (conflict-free transpose) ----
    float4 pf[8];
    float4 sqpre;
    auto ldchunk = [&](int t) {
        #pragma unroll
        for (int i = 0; i < 8; i++) {
            int s  = lane + 32 * (i & 3);
            int kg = 2 * w + (i >> 2);
            pf[i] = *(const float4*)(S + (size_t)(t * ST + s) * DIM + kg * 4);
        }
        if (tid < 32)
            sqpre = *(const float4*)(g_sq_s + t * ST + tid * 4);
    };
    auto stchunk = [&](int buf) {
        float* dst = Ssm + buf * (64 * 128);
        #pragma unroll
        for (int i = 0; i < 8; i++) {
            int s  = lane + 32 * (i & 3);
            int kg = 2 * w + (i >> 2);
            int phys = (((s >> 2) ^ (kg & 7)) << 2) | (s & 3);
            float vv[4] = {pf[i].x, pf[i].y, pf[i].z, pf[i].w};
            #pragma unroll
            for (int cc = 0; cc < 4; cc++)
                dst[(kg * 4 + cc) * 128 + phys] = vv[cc];
        }
        if (tid < 32)
            *(float4*)(sqs_sm + buf * 128 + tid * 4) = sqpre;
    };

    ldchunk(0);
    stchunk(0);
    ldchunk(1);
    __syncthreads();

    float m1[4];
    int   i1[4];
    #pragma unroll
    for (int i = 0; i < 4; i++) { m1[i] = FLT_MAX; i1[i] = 0; }

    const unsigned long long NEG2 = 0xC0000000C0000000ull;
    const float* qb = Qdup + qs * 64 + qg * 8;
    const int g0 = ss * 8 + sg * 2;

    for (int t = 0; t < NCHUNK; t++) {
        const int buf = t & 1;
        if (t + 1 < NCHUNK) stchunk(buf ^ 1);      // write chunk t+1
        if (t + 2 < NCHUNK) ldchunk(t + 2);        // prefetch chunk t+2

        unsigned long long acc[4][4];
        #pragma unroll
        for (int i = 0; i < 4; i++)
            #pragma unroll
            for (int j = 0; j < 4; j++) acc[i][j] = 0ull;

        const float* sb = Ssm + buf * (64 * 128);

        #pragma unroll 8
        for (int k = 0; k < DIM; k++) {
            const int f = (k >> 2) & 7;
            ulonglong2 qa = *(const ulonglong2*)(qb + k * 128);
            ulonglong2 qc = *(const ulonglong2*)(qb + k * 128 + 4);
            const float* sp = sb + k * 128;
            ulonglong2 sa = *(const ulonglong2*)(sp + ((g0 ^ f) << 2));
            ulonglong2 sc = *(const ulonglong2*)(sp + (((g0 + 1) ^ f) << 2));
            unsigned long long qv[4] = {qa.x, qa.y, qc.x, qc.y};
            unsigned long long sv[4] = {sa.x, sa.y, sc.x, sc.y};
            #pragma unroll
            for (int i = 0; i < 4; i++)
                #pragma unroll
                for (int j = 0; j < 4; j++)
                    acc[i][j] = fma2(qv[i], sv[j], acc[i][j]);
        }

        // epilogue: d2' = ||s||^2 - 2*cross; first-min with ascending s
        const float* sq = sqs_sm + buf * 128 + ss * 32 + sg * 8;
        const int sb0 = t * ST + ss * 32 + sg * 8;
        #pragma unroll
        for (int j = 0; j < 4; j++) {
            unsigned long long sqp = *(const unsigned long long*)(sq + 2 * j);
            const int idx = sb0 + 2 * j;
            #pragma unroll
            for (int i = 0; i < 4; i++) {
                unsigned long long d2 = fma2(NEG2, acc[i][j], sqp);
                float lo = __uint_as_float((unsigned)(d2 & 0xffffffffull));
                float hi = __uint_as_float((unsigned)(d2 >> 32));
                if (lo < m1[i]) { m1[i] = lo; i1[i] = idx; }
                if (hi < m1[i]) { m1[i] = hi; i1[i] = idx + 1; }
            }
        }
        __syncthreads();
    }

    // ---- reduce over sg (4 lanes per query within warp) ----
    float* pm = (float*)(smem + OFF_PM);   // [4 ss][64 q]
    int*   pi = (int*)(smem + OFF_PI);
    int*   lab = (int*)(smem + OFF_LAB);
    #pragma unroll
    for (int i = 0; i < 4; i++) {
        float d = m1[i];
        int   x = i1[i];
        #pragma unroll
        for (int off = 8; off <= 16; off <<= 1) {
            float od = __shfl_xor_sync(0xffffffffu, d, off);
            int   ox = __shfl_xor_sync(0xffffffffu, x, off);
            if (od < d || (od == d && ox < x)) { d = od; x = ox; }
        }
        if (sg == 0) {
            pm[ss * 64 + qs * 32 + qg * 4 + i] = d;
            pi[ss * 64 + qs * 32 + qg * 4 + i] = x;
        }
    }
    __syncthreads();

    // ---- merge 4 support strips per query (ascending ss = ascending s) ----
    if (tid < QT) {
        float d = pm[tid];
        int   x = pi[tid];
        #pragma unroll
        for (int s = 1; s < 4; s++) {
            float od = pm[s * 64 + tid];
            int   ox = pi[s * 64 + tid];
            if (od < d || (od == d && ox < x)) { d = od; x = ox; }
        }
        lab[tid] = g_lab[x];
    }
    __syncthreads();

    // ---- one-hot write: 64 rows x 64 cols ----
    #pragma unroll
    for (int j = 0; j < 4; j++) {
        int g = tid + j * 256;
        int row = g >> 4;
        int c4 = (g & 15) * 4;
        int lb = lab[row];
        float4 v;
        v.x = (c4 + 0 == lb) ? 1.f : 0.f;
        v.y = (c4 + 1 == lb) ? 1.f : 0.f;
        v.z = (c4 + 2 == lb) ? 1.f : 0.f;
        v.w = (c4 + 3 == lb) ? 1.f : 0.f;
        *(float4*)(out + (size_t)(qbase + row) * NC + c4) = v;
    }
}

// ---------------- launch ----------------
extern "C" void kernel_launch(void* const* d_in, const int* in_sizes, int n_in,
                              void* d_out, int out_size) {
    const float* S  = (const float*)d_in[0];
    const float* Q  = (const float*)d_in[1];
    const float* OH = (const float*)d_in[2];
    float* out = (float*)d_out;

    static bool attr_set = false;
    if (!attr_set) {
        cudaFuncSetAttribute(knn_kernel,
                             cudaFuncAttributeMaxDynamicSharedMemorySize, SMEM_SZ);
        attr_set = true;
    }

    prep_kernel<<<NS / 64, 256>>>(S, OH);
    knn_kernel<<<NQ / QT, 256, SMEM_SZ>>>(S, Q, out);
}